// round 2
// baseline (speedup 1.0000x reference)
#include <cuda_runtime.h>

#define NN 2048
#define DD 128
#define HH 40
#define BM 64
#define BN 64

// Scratch (static __device__ arrays per harness rules)
__device__ float g_Q [HH * NN * DD];   // per-head Q = X @ W[h]
__device__ float g_XV[HH * NN * DD];   // per-head XV = X @ V[h]
__device__ float g_O [HH * NN * DD];   // per-head attention output
__device__ float g_cs[HH * DD];        // per-head column sums of XV

// ---------------------------------------------------------------------------
// Kernel 1: per-head projections.  grid (N/BM, H, 2): z=0 -> Q=X@W, z=1 -> XV=X@V
// 256 threads compute a 64x128 output tile, K chunked by 32.
// ---------------------------------------------------------------------------
__global__ void precompute_kernel(const float* __restrict__ X,
                                  const float* __restrict__ W,
                                  const float* __restrict__ V) {
    __shared__ float As[BM][33];     // 64x32 X chunk (pad 33)
    __shared__ float Bs[32][129];    // 32x128 W/V chunk (pad 129)

    int rb = blockIdx.x, h = blockIdx.y, z = blockIdx.z;
    const float* B = (z ? V : W) + h * DD * DD;
    float* Out = (z ? g_XV : g_Q) + h * NN * DD + rb * BM * DD;

    int tid = threadIdx.x;
    int ty = tid >> 4, tx = tid & 15;

    float acc[4][8];
    #pragma unroll
    for (int i = 0; i < 4; i++)
        #pragma unroll
        for (int j = 0; j < 8; j++) acc[i][j] = 0.f;

    for (int k0 = 0; k0 < DD; k0 += 32) {
        // Load A tile: 64x32 (coalesced, one row per warp per step)
        #pragma unroll
        for (int i = 0; i < 8; i++) {
            int e = tid + i * 256;
            int r = e >> 5, c = e & 31;
            As[r][c] = X[(rb * BM + r) * DD + k0 + c];
        }
        // Load B tile: 32x128 (coalesced)
        #pragma unroll
        for (int i = 0; i < 16; i++) {
            int e = tid + i * 256;
            int r = e >> 7, c = e & 127;
            Bs[r][c] = B[(k0 + r) * DD + c];
        }
        __syncthreads();

        #pragma unroll
        for (int kk = 0; kk < 32; kk++) {
            float a[4], b[8];
            #pragma unroll
            for (int i = 0; i < 4; i++) a[i] = As[ty * 4 + i][kk];
            #pragma unroll
            for (int j = 0; j < 8; j++) b[j] = Bs[kk][tx + 16 * j];
            #pragma unroll
            for (int i = 0; i < 4; i++)
                #pragma unroll
                for (int j = 0; j < 8; j++) acc[i][j] += a[i] * b[j];
        }
        __syncthreads();
    }

    #pragma unroll
    for (int i = 0; i < 4; i++)
        #pragma unroll
        for (int j = 0; j < 8; j++)
            Out[(ty * 4 + i) * DD + tx + 16 * j] = acc[i][j];
}

// ---------------------------------------------------------------------------
// Kernel 2: per-head column sums of XV.  grid (H), 128 threads.
// ---------------------------------------------------------------------------
__global__ void colsum_kernel() {
    int h = blockIdx.x;
    int c = threadIdx.x;
    const float* p = g_XV + h * NN * DD + c;
    float s = 0.f;
    for (int m = 0; m < NN; m++) s += p[m * DD];
    g_cs[h * DD + c] = s;
}

// ---------------------------------------------------------------------------
// Kernel 3: flash attention per (row-block, head).  grid (N/BM, H), 256 thr.
// Single-pass exp (scores bounded |s|<~0.6, no max-subtraction needed).
// Deterministic denominator reduction (no float atomics).
// Dynamic smem = 90112 B  -> 2 CTAs/SM.
// ---------------------------------------------------------------------------
__global__ void attn_kernel(const float* __restrict__ X) {
    extern __shared__ float sm[];
    float* Qs  = sm;               // [64][132]
    float* KV  = Qs + BM * 132;    // K^T as [128][69], reused as V [64][132]
    float* Ps  = KV + DD * 69;     // [64][65] exp(scores) tile
    float* dsm = Ps + BM * 65;     // [64][17] denominator partials

    int rb = blockIdx.x, h = blockIdx.y;
    int tid = threadIdx.x;
    int ty = tid >> 4, tx = tid & 15;

    const float* Qg = g_Q  + h * NN * DD + rb * BM * DD;
    const float* Vg = g_XV + h * NN * DD;

    // Load Q tile 64x128 into padded smem
    #pragma unroll
    for (int i = 0; i < 32; i++) {
        int e = tid + i * 256;
        int r = e >> 7, c = e & 127;
        Qs[r * 132 + c] = Qg[e];
    }

    float acc[4][8];
    float dpart[4];
    #pragma unroll
    for (int i = 0; i < 4; i++) {
        dpart[i] = 0.f;
        #pragma unroll
        for (int j = 0; j < 8; j++) acc[i][j] = 0.f;
    }

    const float scale = 0.08838834764831845f;  // 1/sqrt(128)

    for (int t = 0; t < NN / BN; t++) {
        __syncthreads();   // prior PV done reading KV & Ps

        // Load K tile transposed: KT[k][row], stride 69 (conflict-free store)
        const float* Kg = X + t * BN * DD;
        #pragma unroll
        for (int i = 0; i < 32; i++) {
            int e = tid + i * 256;
            int r = e >> 7, c = e & 127;      // r = key row, c = k
            KV[c * 69 + r] = Kg[e];
        }
        __syncthreads();

        // S = Q K^T : thread owns rows ty*4+i, key-cols tx+16*j (j<4)
        float s[4][4];
        #pragma unroll
        for (int i = 0; i < 4; i++)
            #pragma unroll
            for (int j = 0; j < 4; j++) s[i][j] = 0.f;

        #pragma unroll 4
        for (int k = 0; k < DD; k++) {
            float q[4], kb[4];
            #pragma unroll
            for (int i = 0; i < 4; i++) q[i] = Qs[(ty * 4 + i) * 132 + k];
            #pragma unroll
            for (int j = 0; j < 4; j++) kb[j] = KV[k * 69 + tx + 16 * j];
            #pragma unroll
            for (int i = 0; i < 4; i++)
                #pragma unroll
                for (int j = 0; j < 4; j++) s[i][j] += q[i] * kb[j];
        }

        // exp + write P tile + accumulate denominator partials in registers
        #pragma unroll
        for (int i = 0; i < 4; i++) {
            float rs = 0.f;
            #pragma unroll
            for (int j = 0; j < 4; j++) {
                float p = __expf(s[i][j] * scale);
                Ps[(ty * 4 + i) * 65 + tx + 16 * j] = p;
                rs += p;
            }
            dpart[i] += rs;
        }
        __syncthreads();   // Ps ready; K reads done, KV reusable

        // Load V tile 64x128 row-major (stride 132)
        const float* Vt = Vg + t * BN * DD;
        #pragma unroll
        for (int i = 0; i < 32; i++) {
            int e = tid + i * 256;
            int r = e >> 7, c = e & 127;
            KV[r * 132 + c] = Vt[e];
        }
        __syncthreads();

        // O += P @ V : thread owns rows ty*4+i, out-cols tx+16*j (j<8)
        #pragma unroll 2
        for (int k = 0; k < BN; k++) {
            float p[4], v[8];
            #pragma unroll
            for (int i = 0; i < 4; i++) p[i] = Ps[(ty * 4 + i) * 65 + k];
            #pragma unroll
            for (int j = 0; j < 8; j++) v[j] = KV[k * 132 + tx + 16 * j];
            #pragma unroll
            for (int i = 0; i < 4; i++)
                #pragma unroll
                for (int j = 0; j < 8; j++) acc[i][j] += p[i] * v[j];
        }
    }

    // Deterministic denominator reduction
    #pragma unroll
    for (int i = 0; i < 4; i++) dsm[(ty * 4 + i) * 17 + tx] = dpart[i];
    __syncthreads();

    float* Og = g_O + h * NN * DD + rb * BM * DD;
    #pragma unroll
    for (int i = 0; i < 4; i++) {
        int r = ty * 4 + i;
        float dsum = 0.f;
        #pragma unroll
        for (int x = 0; x < 16; x++) dsum += dsm[r * 17 + x];
        float inv = 1.f / dsum;
        #pragma unroll
        for (int j = 0; j < 8; j++)
            Og[r * DD + tx + 16 * j] = acc[i][j] * inv;
    }
}

// ---------------------------------------------------------------------------
// Kernel 4: sum over heads + 1e-8 * colsum correction -> d_out
// ---------------------------------------------------------------------------
__global__ void reduce_kernel(float* __restrict__ out) {
    int idx = blockIdx.x * 256 + threadIdx.x;   // 0 .. N*D-1
    int c = idx & 127;
    float s = 0.f;
    #pragma unroll 4
    for (int h = 0; h < HH; h++)
        s += g_O[h * NN * DD + idx] + 1e-8f * g_cs[h * DD + c];
    out[idx] = s;
}

// ---------------------------------------------------------------------------
extern "C" void kernel_launch(void* const* d_in, const int* in_sizes, int n_in,
                              void* d_out, int out_size) {
    const float* X = (const float*)d_in[0];
    const float* W = (const float*)d_in[1];
    const float* V = (const float*)d_in[2];
    float* out = (float*)d_out;

    precompute_kernel<<<dim3(NN / BM, HH, 2), 256>>>(X, W, V);
    colsum_kernel<<<HH, 128>>>();

    const size_t smem_bytes = (BM * 132 + DD * 69 + BM * 65 + BM * 17) * sizeof(float); // 90112
    cudaFuncSetAttribute(attn_kernel, cudaFuncAttributeMaxDynamicSharedMemorySize,
                         (int)smem_bytes);
    attn_kernel<<<dim3(NN / BM, HH), 256, smem_bytes>>>(X);

    reduce_kernel<<<(NN * DD) / 256, 256>>>(out);
}

// round 3
// speedup vs baseline: 4.1765x; 4.1765x over previous
#include <cuda_runtime.h>
#include <cuda_fp16.h>

#define NN 2048
#define DD 128
#define HH 40

// Scratch (static __device__ arrays per harness rules)
__device__ __half g_Qh [HH * NN * DD];   // fp16 Q = X @ W[h]
__device__ __half g_XVh[HH * NN * DD];   // fp16 XV
__device__ float  g_XV [HH * NN * DD];   // fp32 XV (exact, for colsum)
__device__ float  g_O  [HH * NN * DD];   // per-head attention output
__device__ __half g_Xh [NN * DD];        // fp16 X (keys)
__device__ float  g_cs [HH * DD];        // per-head column sums of XV (fp32)

// ---------------------------------------------------------------------------
// X -> fp16 conversion
// ---------------------------------------------------------------------------
__global__ void xconv_kernel(const float* __restrict__ X) {
    int i = blockIdx.x * 256 + threadIdx.x;
    g_Xh[i] = __float2half_rn(X[i]);
}

// ---------------------------------------------------------------------------
// Kernel 1: per-head projections (fp32 FFMA, emits fp16 + fp32 copies).
// grid (N/64, H, 2): z=0 -> Q=X@W (fp16 only), z=1 -> XV=X@V (fp16 + fp32)
// ---------------------------------------------------------------------------
__global__ void precompute_kernel(const float* __restrict__ X,
                                  const float* __restrict__ W,
                                  const float* __restrict__ V) {
    __shared__ float As[64][33];
    __shared__ float Bs[32][129];

    int rb = blockIdx.x, h = blockIdx.y, z = blockIdx.z;
    const float* B = (z ? V : W) + h * DD * DD;

    int tid = threadIdx.x;
    int ty = tid >> 4, tx = tid & 15;

    float acc[4][8];
    #pragma unroll
    for (int i = 0; i < 4; i++)
        #pragma unroll
        for (int j = 0; j < 8; j++) acc[i][j] = 0.f;

    for (int k0 = 0; k0 < DD; k0 += 32) {
        #pragma unroll
        for (int i = 0; i < 8; i++) {
            int e = tid + i * 256;
            int r = e >> 5, c = e & 31;
            As[r][c] = X[(rb * 64 + r) * DD + k0 + c];
        }
        #pragma unroll
        for (int i = 0; i < 16; i++) {
            int e = tid + i * 256;
            int r = e >> 7, c = e & 127;
            Bs[r][c] = B[(k0 + r) * DD + c];
        }
        __syncthreads();

        #pragma unroll
        for (int kk = 0; kk < 32; kk++) {
            float a[4], b[8];
            #pragma unroll
            for (int i = 0; i < 4; i++) a[i] = As[ty * 4 + i][kk];
            #pragma unroll
            for (int j = 0; j < 8; j++) b[j] = Bs[kk][tx + 16 * j];
            #pragma unroll
            for (int i = 0; i < 4; i++)
                #pragma unroll
                for (int j = 0; j < 8; j++) acc[i][j] += a[i] * b[j];
        }
        __syncthreads();
    }

    size_t base = (size_t)h * NN * DD + (size_t)rb * 64 * DD;
    if (z) {
        float*  Of = g_XV  + base;
        __half* Oh = g_XVh + base;
        #pragma unroll
        for (int i = 0; i < 4; i++)
            #pragma unroll
            for (int j = 0; j < 8; j++) {
                int idx = (ty * 4 + i) * DD + tx + 16 * j;
                Of[idx] = acc[i][j];
                Oh[idx] = __float2half_rn(acc[i][j]);
            }
    } else {
        __half* Oh = g_Qh + base;
        #pragma unroll
        for (int i = 0; i < 4; i++)
            #pragma unroll
            for (int j = 0; j < 8; j++)
                Oh[(ty * 4 + i) * DD + tx + 16 * j] = __float2half_rn(acc[i][j]);
    }
}

// ---------------------------------------------------------------------------
// Kernel 2: per-head column sums of fp32 XV.  grid (H), 128 threads.
// ---------------------------------------------------------------------------
__global__ void colsum_kernel() {
    int h = blockIdx.x;
    int c = threadIdx.x;
    const float* p = g_XV + (size_t)h * NN * DD + c;
    float s = 0.f;
    for (int m = 0; m < NN; m++) s += p[m * DD];
    g_cs[h * DD + c] = s;
}

// ---------------------------------------------------------------------------
// mma.sync m16n8k16 fp16 -> fp32
// ---------------------------------------------------------------------------
__device__ __forceinline__ void mma16816(float (&c)[4], const unsigned (&a)[4],
                                         unsigned b0, unsigned b1) {
    asm volatile(
        "mma.sync.aligned.m16n8k16.row.col.f32.f16.f16.f32 "
        "{%0,%1,%2,%3}, {%4,%5,%6,%7}, {%8,%9}, {%0,%1,%2,%3};\n"
        : "+f"(c[0]), "+f"(c[1]), "+f"(c[2]), "+f"(c[3])
        : "r"(a[0]), "r"(a[1]), "r"(a[2]), "r"(a[3]), "r"(b0), "r"(b1));
}

// ---------------------------------------------------------------------------
// Kernel 3: tensor-core flash attention.  grid (N/128, H), 256 threads.
// O_num = colsum + sum_m (exp(s)-1) * V   (P = 1 + p' decomposition)
// smem strides: Q/K/V rows 136 halfs, P rows 72 halfs (conflict-free).
// ---------------------------------------------------------------------------
#define SQ_STRIDE 136
#define SP_STRIDE 72

__global__ __launch_bounds__(256, 1) void attn_kernel() {
    extern __shared__ __half sh[];
    __half* sQ = sh;                       // 128 x 136
    __half* sK = sQ + 128 * SQ_STRIDE;     // 64 x 136
    __half* sV = sK + 64 * SQ_STRIDE;      // 64 x 136
    __half* sP = sV + 64 * SQ_STRIDE;      // 128 x 72
    float* dsm = (float*)(sP + 128 * SP_STRIDE);   // [128][8]

    int rb = blockIdx.x, h = blockIdx.y;
    int tid = threadIdx.x;
    int wid = tid >> 5, lane = tid & 31;
    int wm = wid >> 1, wn = wid & 1;       // warp grid 4 x 2
    int g = lane >> 2, t = lane & 3;

    const size_t hbase = (size_t)h * NN * DD;

    // Load Q tile 128x128 (uint4 = 8 halfs each)
    {
        const uint4* Q4 = (const uint4*)(g_Qh + hbase + (size_t)rb * 128 * DD);
        #pragma unroll
        for (int j = 0; j < 8; j++) {
            int u = tid + j * 256;
            int row = u >> 4, c8 = u & 15;
            *(uint4*)&sQ[row * SQ_STRIDE + c8 * 8] = Q4[u];
        }
    }

    float oc[2][8][4];
    #pragma unroll
    for (int mi = 0; mi < 2; mi++)
        #pragma unroll
        for (int ni = 0; ni < 8; ni++)
            #pragma unroll
            for (int c = 0; c < 4; c++) oc[mi][ni][c] = 0.f;

    float dpart[2][2] = {{0.f, 0.f}, {0.f, 0.f}};
    const float scale = 0.08838834764831845f;   // 1/sqrt(128)

    const uint4* K4base = (const uint4*)g_Xh;
    const uint4* V4base = (const uint4*)(g_XVh + hbase);

    for (int kt = 0; kt < NN / 64; kt++) {
        __syncthreads();   // previous iteration's PV reads done

        // Load K tile (64x128) and V tile (64x128)
        #pragma unroll
        for (int j = 0; j < 4; j++) {
            int u = tid + j * 256;
            int row = u >> 4, c8 = u & 15;
            *(uint4*)&sK[row * SQ_STRIDE + c8 * 8] = K4base[kt * 1024 + u];
            *(uint4*)&sV[row * SQ_STRIDE + c8 * 8] = V4base[kt * 1024 + u];
        }
        __syncthreads();

        // ---- QK: S tile 128x64, warp tile 32x32 at (wm*32, wn*32) ----
        float sc[2][4][4];
        #pragma unroll
        for (int mi = 0; mi < 2; mi++)
            #pragma unroll
            for (int ni = 0; ni < 4; ni++)
                #pragma unroll
                for (int c = 0; c < 4; c++) sc[mi][ni][c] = 0.f;

        #pragma unroll
        for (int kf = 0; kf < 8; kf++) {
            int k0 = kf * 16;
            unsigned a[2][4];
            #pragma unroll
            for (int mi = 0; mi < 2; mi++) {
                int row = wm * 32 + mi * 16 + g;
                a[mi][0] = *(const unsigned*)&sQ[row * SQ_STRIDE + k0 + 2 * t];
                a[mi][1] = *(const unsigned*)&sQ[(row + 8) * SQ_STRIDE + k0 + 2 * t];
                a[mi][2] = *(const unsigned*)&sQ[row * SQ_STRIDE + k0 + 8 + 2 * t];
                a[mi][3] = *(const unsigned*)&sQ[(row + 8) * SQ_STRIDE + k0 + 8 + 2 * t];
            }
            #pragma unroll
            for (int ni = 0; ni < 4; ni++) {
                int n = wn * 32 + ni * 8 + g;
                unsigned b0 = *(const unsigned*)&sK[n * SQ_STRIDE + k0 + 2 * t];
                unsigned b1 = *(const unsigned*)&sK[n * SQ_STRIDE + k0 + 8 + 2 * t];
                #pragma unroll
                for (int mi = 0; mi < 2; mi++)
                    mma16816(sc[mi][ni], a[mi], b0, b1);
            }
        }

        // ---- exp, p' = exp-1, denom partials, stage p' to smem ----
        #pragma unroll
        for (int mi = 0; mi < 2; mi++) {
            int row = wm * 32 + mi * 16 + g;
            #pragma unroll
            for (int ni = 0; ni < 4; ni++) {
                int col = wn * 32 + ni * 8 + 2 * t;
                float p0 = __expf(sc[mi][ni][0] * scale);
                float p1 = __expf(sc[mi][ni][1] * scale);
                float p2 = __expf(sc[mi][ni][2] * scale);
                float p3 = __expf(sc[mi][ni][3] * scale);
                dpart[mi][0] += p0 + p1;
                dpart[mi][1] += p2 + p3;
                *(__half2*)&sP[row * SP_STRIDE + col] =
                    __floats2half2_rn(p0 - 1.f, p1 - 1.f);
                *(__half2*)&sP[(row + 8) * SP_STRIDE + col] =
                    __floats2half2_rn(p2 - 1.f, p3 - 1.f);
            }
        }
        __syncthreads();   // sP complete

        // ---- PV: O += p' @ V.  Warp tile 32 rows x 64 cols at (wm*32, wn*64)
        #pragma unroll
        for (int kf = 0; kf < 4; kf++) {
            int k0 = kf * 16;
            unsigned a2[2][4];
            #pragma unroll
            for (int mi = 0; mi < 2; mi++) {
                int row = wm * 32 + mi * 16 + g;
                a2[mi][0] = *(const unsigned*)&sP[row * SP_STRIDE + k0 + 2 * t];
                a2[mi][1] = *(const unsigned*)&sP[(row + 8) * SP_STRIDE + k0 + 2 * t];
                a2[mi][2] = *(const unsigned*)&sP[row * SP_STRIDE + k0 + 8 + 2 * t];
                a2[mi][3] = *(const unsigned*)&sP[(row + 8) * SP_STRIDE + k0 + 8 + 2 * t];
            }
            #pragma unroll
            for (int ni = 0; ni < 8; ni++) {
                int n = wn * 64 + ni * 8 + g;
                int ka = k0 + 2 * t;
                unsigned b0 = (unsigned)__half_as_ushort(sV[ka * SQ_STRIDE + n]) |
                              ((unsigned)__half_as_ushort(sV[(ka + 1) * SQ_STRIDE + n]) << 16);
                unsigned b1 = (unsigned)__half_as_ushort(sV[(ka + 8) * SQ_STRIDE + n]) |
                              ((unsigned)__half_as_ushort(sV[(ka + 9) * SQ_STRIDE + n]) << 16);
                #pragma unroll
                for (int mi = 0; mi < 2; mi++)
                    mma16816(oc[mi][ni], a2[mi], b0, b1);
            }
        }
    }

    // ---- deterministic denominator reduction ----
    __syncthreads();
    #pragma unroll
    for (int mi = 0; mi < 2; mi++) {
        int row = wm * 32 + mi * 16 + g;
        dsm[row * 8 + wn * 4 + t]       = dpart[mi][0];
        dsm[(row + 8) * 8 + wn * 4 + t] = dpart[mi][1];
    }
    __syncthreads();

    // ---- epilogue: (colsum + p'V) / denom -> g_O ----
    const float* cs = g_cs + h * DD;
    float* Og = g_O + hbase + (size_t)rb * 128 * DD;
    #pragma unroll
    for (int mi = 0; mi < 2; mi++) {
        #pragma unroll
        for (int hh = 0; hh < 2; hh++) {
            int row = wm * 32 + mi * 16 + g + 8 * hh;
            float dsum = 0.f;
            #pragma unroll
            for (int x = 0; x < 8; x++) dsum += dsm[row * 8 + x];
            float inv = 1.f / dsum;
            #pragma unroll
            for (int ni = 0; ni < 8; ni++) {
                int col = wn * 64 + ni * 8 + 2 * t;
                Og[row * DD + col]     = (oc[mi][ni][2 * hh]     + cs[col])     * inv;
                Og[row * DD + col + 1] = (oc[mi][ni][2 * hh + 1] + cs[col + 1]) * inv;
            }
        }
    }
}

// ---------------------------------------------------------------------------
// Kernel 4: sum over heads + 1e-8 * colsum correction -> d_out
// ---------------------------------------------------------------------------
__global__ void reduce_kernel(float* __restrict__ out) {
    int idx = blockIdx.x * 256 + threadIdx.x;
    int c = idx & 127;
    float s = 0.f;
    #pragma unroll 4
    for (int h = 0; h < HH; h++)
        s += g_O[(size_t)h * NN * DD + idx] + 1e-8f * g_cs[h * DD + c];
    out[idx] = s;
}

// ---------------------------------------------------------------------------
extern "C" void kernel_launch(void* const* d_in, const int* in_sizes, int n_in,
                              void* d_out, int out_size) {
    const float* X = (const float*)d_in[0];
    const float* W = (const float*)d_in[1];
    const float* V = (const float*)d_in[2];
    float* out = (float*)d_out;

    xconv_kernel<<<NN * DD / 256, 256>>>(X);
    precompute_kernel<<<dim3(NN / 64, HH, 2), 256>>>(X, W, V);
    colsum_kernel<<<HH, 128>>>();

    const size_t smem_bytes =
        (size_t)(128 * SQ_STRIDE + 64 * SQ_STRIDE + 64 * SQ_STRIDE + 128 * SP_STRIDE)
            * sizeof(__half) + 128 * 8 * sizeof(float);   // 92160 B
    cudaFuncSetAttribute(attn_kernel, cudaFuncAttributeMaxDynamicSharedMemorySize,
                         (int)smem_bytes);
    attn_kernel<<<dim3(NN / 128, HH), 256, smem_bytes>>>();

    reduce_kernel<<<(NN * DD) / 256, 256>>>(out);
}

// round 6
// speedup vs baseline: 5.0747x; 1.2151x over previous
#include <cuda_runtime.h>
#include <cuda_fp16.h>
#include <cstdint>

#define NN 2048
#define DD 128
#define HH 40

// Scratch (static __device__ arrays per harness rules)
__device__ __align__(16) __half g_Qh [HH * NN * DD];   // per-head Q (fp16)
__device__ __align__(16) __half g_XVh[HH * NN * DD];   // per-head XV (fp16, row-major)
__device__ __align__(16) __half g_XVt[HH * NN * DD];   // per-head XV^T (fp16, [d][m])
__device__ __align__(16) float  g_XV [HH * NN * DD];   // fp32 XV (exact, for colsum)
__device__ __align__(16) float  g_O  [HH * NN * DD];   // per-head attention output
__device__ __align__(16) __half g_Xh [NN * DD];        // fp16 X (keys)
__device__ float g_cs [HH * DD];
__device__ float g_csp[HH * 8 * DD];

// ---------------------------------------------------------------------------
__global__ void xconv_kernel(const float* __restrict__ X) {
    int i = blockIdx.x * 256 + threadIdx.x;
    g_Xh[i] = __float2half_rn(X[i]);
}

// ---------------------------------------------------------------------------
// Per-head projections (fp32 FFMA) -> g_Qh (fp16), g_XVh (fp16), g_XV (fp32)
// ---------------------------------------------------------------------------
__global__ void precompute_kernel(const float* __restrict__ X,
                                  const float* __restrict__ W,
                                  const float* __restrict__ V) {
    __shared__ float As[64][33];
    __shared__ float Bs[32][129];

    int rb = blockIdx.x, h = blockIdx.y, z = blockIdx.z;
    const float* B = (z ? V : W) + h * DD * DD;

    int tid = threadIdx.x;
    int ty = tid >> 4, tx = tid & 15;

    float acc[4][8];
    #pragma unroll
    for (int i = 0; i < 4; i++)
        #pragma unroll
        for (int j = 0; j < 8; j++) acc[i][j] = 0.f;

    for (int k0 = 0; k0 < DD; k0 += 32) {
        #pragma unroll
        for (int i = 0; i < 8; i++) {
            int e = tid + i * 256;
            int r = e >> 5, c = e & 31;
            As[r][c] = X[(rb * 64 + r) * DD + k0 + c];
        }
        #pragma unroll
        for (int i = 0; i < 16; i++) {
            int e = tid + i * 256;
            int r = e >> 7, c = e & 127;
            Bs[r][c] = B[(k0 + r) * DD + c];
        }
        __syncthreads();

        #pragma unroll
        for (int kk = 0; kk < 32; kk++) {
            float a[4], b[8];
            #pragma unroll
            for (int i = 0; i < 4; i++) a[i] = As[ty * 4 + i][kk];
            #pragma unroll
            for (int j = 0; j < 8; j++) b[j] = Bs[kk][tx + 16 * j];
            #pragma unroll
            for (int i = 0; i < 4; i++)
                #pragma unroll
                for (int j = 0; j < 8; j++) acc[i][j] += a[i] * b[j];
        }
        __syncthreads();
    }

    size_t base = (size_t)h * NN * DD + (size_t)rb * 64 * DD;
    if (z) {
        float*  Of = g_XV  + base;
        __half* Oh = g_XVh + base;
        #pragma unroll
        for (int i = 0; i < 4; i++)
            #pragma unroll
            for (int j = 0; j < 8; j++) {
                int idx = (ty * 4 + i) * DD + tx + 16 * j;
                Of[idx] = acc[i][j];
                Oh[idx] = __float2half_rn(acc[i][j]);
            }
    } else {
        __half* Oh = g_Qh + base;
        #pragma unroll
        for (int i = 0; i < 4; i++)
            #pragma unroll
            for (int j = 0; j < 8; j++)
                Oh[(ty * 4 + i) * DD + tx + 16 * j] = __float2half_rn(acc[i][j]);
    }
}

// ---------------------------------------------------------------------------
// Transpose g_XVh -> g_XVt per head.  grid (64, 4, 40), block (32, 8).
// ---------------------------------------------------------------------------
__global__ void transpose_kernel() {
    __shared__ __half tile[32][33];
    int h = blockIdx.z;
    int m0 = blockIdx.x * 32, d0 = blockIdx.y * 32;
    const __half* src = g_XVh + (size_t)h * NN * DD;
    __half* dst = g_XVt + (size_t)h * NN * DD;
    int tx = threadIdx.x, ty = threadIdx.y;
    #pragma unroll
    for (int i = 0; i < 4; i++)
        tile[ty + 8 * i][tx] = src[(size_t)(m0 + ty + 8 * i) * DD + d0 + tx];
    __syncthreads();
    #pragma unroll
    for (int i = 0; i < 4; i++)
        dst[(size_t)(d0 + ty + 8 * i) * NN + m0 + tx] = tile[tx][ty + 8 * i];
}

// ---------------------------------------------------------------------------
// Deterministic two-stage column sums of fp32 XV.
// ---------------------------------------------------------------------------
__global__ void colsum1_kernel() {
    int h = blockIdx.x, part = blockIdx.y;
    int c = threadIdx.x;
    const float* p = g_XV + (size_t)h * NN * DD + (size_t)part * 256 * DD + c;
    float s = 0.f;
    #pragma unroll 4
    for (int m = 0; m < 256; m++) s += p[m * DD];
    g_csp[(h * 8 + part) * DD + c] = s;
}
__global__ void colsum2_kernel() {
    int h = blockIdx.x;
    int c = threadIdx.x;
    float s = 0.f;
    #pragma unroll
    for (int i = 0; i < 8; i++) s += g_csp[(h * 8 + i) * DD + c];
    g_cs[h * DD + c] = s;
}

// ===========================================================================
// helpers
// ===========================================================================
__device__ __forceinline__ uint32_t s2u(const void* p) {
    uint32_t a;
    asm("{ .reg .u64 t; cvta.to.shared.u64 t, %1; cvt.u32.u64 %0, t; }"
        : "=r"(a) : "l"(p));
    return a;
}
__device__ __forceinline__ void cpasync16(uint32_t s, const void* g) {
    asm volatile("cp.async.cg.shared.global [%0], [%1], 16;" :: "r"(s), "l"(g));
}
__device__ __forceinline__ void cp_commit() {
    asm volatile("cp.async.commit_group;" ::: "memory");
}
__device__ __forceinline__ void cp_wait0() {
    asm volatile("cp.async.wait_group 0;" ::: "memory");
}
__device__ __forceinline__ void cp_wait1() {
    asm volatile("cp.async.wait_group 1;" ::: "memory");
}
__device__ __forceinline__ void mma16816(float (&c)[4], const unsigned (&a)[4],
                                         unsigned b0, unsigned b1) {
    asm volatile(
        "mma.sync.aligned.m16n8k16.row.col.f32.f16.f16.f32 "
        "{%0,%1,%2,%3}, {%4,%5,%6,%7}, {%8,%9}, {%0,%1,%2,%3};\n"
        : "+f"(c[0]), "+f"(c[1]), "+f"(c[2]), "+f"(c[3])
        : "r"(a[0]), "r"(a[1]), "r"(a[2]), "r"(a[3]), "r"(b0), "r"(b1));
}
__device__ __forceinline__ float ex2f(float x) {
    float r; asm("ex2.approx.f32 %0, %1;" : "=f"(r) : "f"(x)); return r;
}
__device__ __forceinline__ unsigned packh2(float lo, float hi) {
    unsigned r;
    asm("cvt.rn.f16x2.f32 %0, %1, %2;" : "=r"(r) : "f"(hi), "f"(lo));
    return r;
}

// SMEM layout (bytes).  Q rows: 136 halfs (272B).  K rows: 136 halfs.
// VT rows: 72 halfs (144B).
#define SM_CS   0
#define SM_Q    512
#define SM_K0   35328
#define SM_K1   52736
#define SM_V0   70144
#define SM_V1   88576
#define SM_TOTAL 107008

// ---------------------------------------------------------------------------
// HMMA flash attention, FA2-style register P reuse.
// grid (16, 40), 256 threads (8 warps x 16 query rows).
// ---------------------------------------------------------------------------
__global__ __launch_bounds__(256, 1) void attn_kernel() {
    extern __shared__ char sm[];
    uint32_t sb = s2u(sm);
    int tid = threadIdx.x;
    int wid = tid >> 5, lane = tid & 31;
    int g = lane >> 2, tau = lane & 3;
    int rb = blockIdx.x, h = blockIdx.y;

    const size_t hbase = (size_t)h * NN * DD;
    const uint4* Qg = (const uint4*)(g_Qh + hbase + (size_t)rb * 128 * DD);
    const uint4* Kg = (const uint4*)g_Xh;
    const uint4* Vt = (const uint4*)(g_XVt + hbase);

    if (tid < 128) ((float*)(sm + SM_CS))[tid] = g_cs[h * DD + tid];

    // ---- prologue: Q tile + K0 + VT0 ----
    #pragma unroll
    for (int j = 0; j < 8; j++) {
        int u = tid + j * 256;
        cpasync16(sb + SM_Q + (u >> 4) * 272 + (u & 15) * 16, Qg + u);
    }
    #pragma unroll
    for (int j = 0; j < 4; j++) {
        int u = tid + j * 256;
        cpasync16(sb + SM_K0 + (u >> 4) * 272 + (u & 15) * 16, Kg + u);
        cpasync16(sb + SM_V0 + (u >> 3) * 144 + (u & 7) * 16,
                  Vt + (u >> 3) * 256 + (u & 7));
    }
    cp_commit();
    cp_wait0();
    __syncthreads();

    // ---- Q fragments to registers (32 regs) ----
    const __half* sQ = (const __half*)(sm + SM_Q);
    int r0 = wid * 16 + g;
    unsigned qa[8][4];
    #pragma unroll
    for (int kf = 0; kf < 8; kf++) {
        int k0 = kf * 16 + 2 * tau;
        qa[kf][0] = *(const unsigned*)&sQ[r0 * 136 + k0];
        qa[kf][1] = *(const unsigned*)&sQ[(r0 + 8) * 136 + k0];
        qa[kf][2] = *(const unsigned*)&sQ[r0 * 136 + k0 + 8];
        qa[kf][3] = *(const unsigned*)&sQ[(r0 + 8) * 136 + k0 + 8];
    }

    float oc[16][4];
    #pragma unroll
    for (int j = 0; j < 16; j++)
        #pragma unroll
        for (int c = 0; c < 4; c++) oc[j][c] = 0.f;
    float d0 = 0.f, d1 = 0.f;

    const float cs2 = 0.12751879523595787f;  // (1/sqrt(128)) * log2(e)

    for (int t = 0; t < 32; t++) {
        __syncthreads();   // all warps done reading the buffer we overwrite

        if (t + 1 < 32) {
            uint32_t kb = sb + (((t + 1) & 1) ? SM_K1 : SM_K0);
            uint32_t vb = sb + (((t + 1) & 1) ? SM_V1 : SM_V0);
            const uint4* Kt = Kg + (t + 1) * 1024;
            #pragma unroll
            for (int j = 0; j < 4; j++) {
                int u = tid + j * 256;
                cpasync16(kb + (u >> 4) * 272 + (u & 15) * 16, Kt + u);
                cpasync16(vb + (u >> 3) * 144 + (u & 7) * 16,
                          Vt + (u >> 3) * 256 + (t + 1) * 8 + (u & 7));
            }
            cp_commit();
            cp_wait1();
        } else {
            cp_wait0();
        }
        __syncthreads();

        const __half* sK = (const __half*)(sm + ((t & 1) ? SM_K1 : SM_K0));
        const __half* sV = (const __half*)(sm + ((t & 1) ? SM_V1 : SM_V0));

        // ---- QK: S = Q @ K^T, warp tile 16 x 64 ----
        float sc[8][4];
        #pragma unroll
        for (int j = 0; j < 8; j++)
            #pragma unroll
            for (int c = 0; c < 4; c++) sc[j][c] = 0.f;

        #pragma unroll
        for (int kf = 0; kf < 8; kf++) {
            int k0 = kf * 16 + 2 * tau;
            #pragma unroll
            for (int j = 0; j < 8; j++) {
                int n = j * 8 + g;
                unsigned b0 = *(const unsigned*)&sK[n * 136 + k0];
                unsigned b1 = *(const unsigned*)&sK[n * 136 + k0 + 8];
                mma16816(sc[j], qa[kf], b0, b1);
            }
        }

        // ---- exp, denom, repack S-frags -> PV A-frags (register only) ----
        unsigned pa[4][4];
        #pragma unroll
        for (int j = 0; j < 8; j++) {
            float e0 = ex2f(sc[j][0] * cs2);
            float e1 = ex2f(sc[j][1] * cs2);
            float e2 = ex2f(sc[j][2] * cs2);
            float e3 = ex2f(sc[j][3] * cs2);
            d0 += e0 + e1;
            d1 += e2 + e3;
            pa[j >> 1][(j & 1) * 2]     = packh2(e0 - 1.f, e1 - 1.f);
            pa[j >> 1][(j & 1) * 2 + 1] = packh2(e2 - 1.f, e3 - 1.f);
        }

        // ---- PV: O += p' @ V, warp tile 16 x 128, k = 64 keys ----
        #pragma unroll
        for (int kf = 0; kf < 4; kf++) {
            int k0 = kf * 16 + 2 * tau;
            #pragma unroll
            for (int j = 0; j < 16; j++) {
                int n = j * 8 + g;
                unsigned b0 = *(const unsigned*)&sV[n * 72 + k0];
                unsigned b1 = *(const unsigned*)&sV[n * 72 + k0 + 8];
                mma16816(oc[j], pa[kf], b0, b1);
            }
        }
    }

    // ---- denominator quad-reduction (deterministic) ----
    d0 += __shfl_xor_sync(0xffffffffu, d0, 1);
    d0 += __shfl_xor_sync(0xffffffffu, d0, 2);
    d1 += __shfl_xor_sync(0xffffffffu, d1, 1);
    d1 += __shfl_xor_sync(0xffffffffu, d1, 2);
    float inv0 = 1.f / d0;
    float inv1 = 1.f / d1;

    // ---- epilogue: (p'V + colsum) / denom -> g_O ----
    const float* cs = (const float*)(sm + SM_CS);
    float* Og = g_O + hbase + (size_t)rb * 128 * DD;
    #pragma unroll
    for (int j = 0; j < 16; j++) {
        int c = j * 8 + 2 * tau;
        float2 csv = *(const float2*)&cs[c];
        float2 v0, v1;
        v0.x = (oc[j][0] + csv.x) * inv0;
        v0.y = (oc[j][1] + csv.y) * inv0;
        v1.x = (oc[j][2] + csv.x) * inv1;
        v1.y = (oc[j][3] + csv.y) * inv1;
        *(float2*)&Og[r0 * DD + c] = v0;
        *(float2*)&Og[(r0 + 8) * DD + c] = v1;
    }
}

// ---------------------------------------------------------------------------
__global__ void reduce_kernel(float* __restrict__ out) {
    int idx = blockIdx.x * 256 + threadIdx.x;
    int c = idx & 127;
    float s = 0.f;
    #pragma unroll 4
    for (int h = 0; h < HH; h++)
        s += g_O[(size_t)h * NN * DD + idx] + 1e-8f * g_cs[h * DD + c];
    out[idx] = s;
}

// ---------------------------------------------------------------------------
extern "C" void kernel_launch(void* const* d_in, const int* in_sizes, int n_in,
                              void* d_out, int out_size) {
    const float* X = (const float*)d_in[0];
    const float* W = (const float*)d_in[1];
    const float* V = (const float*)d_in[2];
    float* out = (float*)d_out;

    xconv_kernel<<<NN * DD / 256, 256>>>(X);
    precompute_kernel<<<dim3(NN / 64, HH, 2), 256>>>(X, W, V);
    transpose_kernel<<<dim3(NN / 32, DD / 32, HH), dim3(32, 8)>>>();
    colsum1_kernel<<<dim3(HH, 8), 128>>>();
    colsum2_kernel<<<HH, 128>>>();

    cudaFuncSetAttribute(attn_kernel, cudaFuncAttributeMaxDynamicSharedMemorySize,
                         SM_TOTAL);
    attn_kernel<<<dim3(NN / 128, HH), 256, SM_TOTAL>>>();

    reduce_kernel<<<(NN * DD) / 256, 256>>>(out);
}

// round 7
// speedup vs baseline: 5.8222x; 1.1473x over previous
#include <cuda_runtime.h>
#include <cuda_fp16.h>
#include <cstdint>

#define NN 2048
#define DD 128
#define HH 40

// Scratch (static __device__ arrays per harness rules)
__device__ __align__(16) __half g_Qh [HH * NN * DD];   // per-head Q (fp16)
__device__ __align__(16) __half g_XVt[HH * NN * DD];   // per-head XV^T (fp16, [d][m])
__device__ __align__(16) float  g_O  [HH * NN * DD];   // per-head attention output
__device__ __align__(16) __half g_Xh [NN * DD];        // fp16 X (keys)
__device__ float g_cs [HH * DD];
__device__ float g_csp[HH * 32 * DD];

// ---------------------------------------------------------------------------
__global__ void xconv_kernel(const float* __restrict__ X) {
    int i = blockIdx.x * 256 + threadIdx.x;
    g_Xh[i] = __float2half_rn(X[i]);
}

// ---------------------------------------------------------------------------
// Per-head projections (fp32 FFMA).
// z=0: Q = X@W -> g_Qh (row-major fp16)
// z=1: XV = X@V -> g_XVt (TRANSPOSED fp16, written via smem staging) and
//      per-block exact fp32 column partial sums -> g_csp
// ---------------------------------------------------------------------------
__global__ void precompute_kernel(const float* __restrict__ X,
                                  const float* __restrict__ W,
                                  const float* __restrict__ V) {
    __shared__ __align__(16) char smem_raw[26880];
    float (*As)[33]  = (float(*)[33])smem_raw;            // 64x33  (8448 B)
    float (*Bs)[129] = (float(*)[129])(smem_raw + 8448);  // 32x129 (16512 B)

    int rb = blockIdx.x, h = blockIdx.y, z = blockIdx.z;
    const float* B = (z ? V : W) + h * DD * DD;

    int tid = threadIdx.x;
    int ty = tid >> 4, tx = tid & 15;

    float acc[4][8];
    #pragma unroll
    for (int i = 0; i < 4; i++)
        #pragma unroll
        for (int j = 0; j < 8; j++) acc[i][j] = 0.f;

    for (int k0 = 0; k0 < DD; k0 += 32) {
        #pragma unroll
        for (int i = 0; i < 8; i++) {
            int e = tid + i * 256;
            int r = e >> 5, c = e & 31;
            As[r][c] = X[(rb * 64 + r) * DD + k0 + c];
        }
        #pragma unroll
        for (int i = 0; i < 16; i++) {
            int e = tid + i * 256;
            int r = e >> 7, c = e & 127;
            Bs[r][c] = B[(k0 + r) * DD + c];
        }
        __syncthreads();

        #pragma unroll
        for (int kk = 0; kk < 32; kk++) {
            float a[4], b[8];
            #pragma unroll
            for (int i = 0; i < 4; i++) a[i] = As[ty * 4 + i][kk];
            #pragma unroll
            for (int j = 0; j < 8; j++) b[j] = Bs[kk][tx + 16 * j];
            #pragma unroll
            for (int i = 0; i < 4; i++)
                #pragma unroll
                for (int j = 0; j < 8; j++) acc[i][j] += a[i] * b[j];
        }
        __syncthreads();
    }

    if (z) {
        // ---- transposed fp16 staging + column partial sums ----
        __half* sT = (__half*)smem_raw;             // [128][72] halfs (18432 B)
        float*  sC = (float*)(smem_raw + 18432);    // [16][132] floats (8448 B)

        #pragma unroll
        for (int j = 0; j < 8; j++) {
            float cj = acc[0][j] + acc[1][j] + acc[2][j] + acc[3][j];
            sC[ty * 132 + tx + 16 * j] = cj;
            int e = tx + 16 * j;
            #pragma unroll
            for (int i = 0; i < 4; i++)
                sT[e * 72 + ty * 4 + i] = __float2half_rn(acc[i][j]);
        }
        __syncthreads();

        // coalesced write of the 128x64 transposed tile
        uint4* dst = (uint4*)(g_XVt + (size_t)h * NN * DD);
        #pragma unroll
        for (int q = 0; q < 4; q++) {
            int u = tid + q * 256;          // 1024 uint4
            int e = u >> 3, mc = u & 7;
            dst[e * 256 + rb * 8 + mc] = *(const uint4*)&sT[e * 72 + mc * 8];
        }

        // exact per-block column partial (deterministic order)
        if (tid < 128) {
            float s = 0.f;
            #pragma unroll
            for (int r = 0; r < 16; r++) s += sC[r * 132 + tid];
            g_csp[((size_t)h * 32 + rb) * DD + tid] = s;
        }
    } else {
        __half* Oh = g_Qh + (size_t)h * NN * DD + (size_t)rb * 64 * DD;
        #pragma unroll
        for (int i = 0; i < 4; i++)
            #pragma unroll
            for (int j = 0; j < 8; j++)
                Oh[(ty * 4 + i) * DD + tx + 16 * j] = __float2half_rn(acc[i][j]);
    }
}

// ---------------------------------------------------------------------------
__global__ void colsum2_kernel() {
    int h = blockIdx.x;
    int c = threadIdx.x;
    float s = 0.f;
    #pragma unroll
    for (int i = 0; i < 32; i++) s += g_csp[((size_t)h * 32 + i) * DD + c];
    g_cs[h * DD + c] = s;
}

// ===========================================================================
// helpers
// ===========================================================================
__device__ __forceinline__ uint32_t s2u(const void* p) {
    uint32_t a;
    asm("{ .reg .u64 t; cvta.to.shared.u64 t, %1; cvt.u32.u64 %0, t; }"
        : "=r"(a) : "l"(p));
    return a;
}
__device__ __forceinline__ void cpasync16(uint32_t s, const void* g) {
    asm volatile("cp.async.cg.shared.global [%0], [%1], 16;" :: "r"(s), "l"(g));
}
__device__ __forceinline__ void cp_commit() {
    asm volatile("cp.async.commit_group;" ::: "memory");
}
__device__ __forceinline__ void cp_wait0() {
    asm volatile("cp.async.wait_group 0;" ::: "memory");
}
__device__ __forceinline__ void cp_wait1() {
    asm volatile("cp.async.wait_group 1;" ::: "memory");
}
__device__ __forceinline__ void mma16816(float (&c)[4], const unsigned (&a)[4],
                                         unsigned b0, unsigned b1) {
    asm volatile(
        "mma.sync.aligned.m16n8k16.row.col.f32.f16.f16.f32 "
        "{%0,%1,%2,%3}, {%4,%5,%6,%7}, {%8,%9}, {%0,%1,%2,%3};\n"
        : "+f"(c[0]), "+f"(c[1]), "+f"(c[2]), "+f"(c[3])
        : "r"(a[0]), "r"(a[1]), "r"(a[2]), "r"(a[3]), "r"(b0), "r"(b1));
}
__device__ __forceinline__ float ex2f(float x) {
    float r; asm("ex2.approx.f32 %0, %1;" : "=f"(r) : "f"(x)); return r;
}
__device__ __forceinline__ unsigned packh2(float lo, float hi) {
    unsigned r;
    asm("cvt.rn.f16x2.f32 %0, %1, %2;" : "=r"(r) : "f"(hi), "f"(lo));
    return r;
}

// SMEM layout (bytes). All tiles 128 rows x 136 halfs (272 B rows).
#define SM_CS   0
#define SM_Q    512
#define SM_K0   35328
#define SM_K1   70144
#define SM_V0   104960
#define SM_V1   139776
#define SM_TOTAL 174592

// ---------------------------------------------------------------------------
// HMMA flash attention, FA2-style register P, 128-key tiles.
// grid (16, 40), 256 threads (8 warps x 16 query rows).
// ---------------------------------------------------------------------------
__global__ __launch_bounds__(256, 1) void attn_kernel() {
    extern __shared__ char sm[];
    uint32_t sb = s2u(sm);
    int tid = threadIdx.x;
    int wid = tid >> 5, lane = tid & 31;
    int g = lane >> 2, tau = lane & 3;
    int rb = blockIdx.x, h = blockIdx.y;

    const size_t hbase = (size_t)h * NN * DD;
    const uint4* Qg = (const uint4*)(g_Qh + hbase + (size_t)rb * 128 * DD);
    const uint4* Kg = (const uint4*)g_Xh;
    const uint4* Vt = (const uint4*)(g_XVt + hbase);

    if (tid < 128) ((float*)(sm + SM_CS))[tid] = g_cs[h * DD + tid];

    // ---- prologue: Q + K0 + VT0 (each 128 rows x 16 uint4) ----
    #pragma unroll
    for (int j = 0; j < 8; j++) {
        int u = tid + j * 256;
        uint32_t so = (u >> 4) * 272 + (u & 15) * 16;
        cpasync16(sb + SM_Q  + so, Qg + u);
        cpasync16(sb + SM_K0 + so, Kg + u);
        cpasync16(sb + SM_V0 + so, Vt + (u >> 4) * 256 + (u & 15));
    }
    cp_commit();
    cp_wait0();
    __syncthreads();

    // ---- Q fragments to registers ----
    const __half* sQ = (const __half*)(sm + SM_Q);
    int r0 = wid * 16 + g;
    unsigned qa[8][4];
    #pragma unroll
    for (int kf = 0; kf < 8; kf++) {
        int k0 = kf * 16 + 2 * tau;
        qa[kf][0] = *(const unsigned*)&sQ[r0 * 136 + k0];
        qa[kf][1] = *(const unsigned*)&sQ[(r0 + 8) * 136 + k0];
        qa[kf][2] = *(const unsigned*)&sQ[r0 * 136 + k0 + 8];
        qa[kf][3] = *(const unsigned*)&sQ[(r0 + 8) * 136 + k0 + 8];
    }

    float oc[16][4];
    #pragma unroll
    for (int j = 0; j < 16; j++)
        #pragma unroll
        for (int c = 0; c < 4; c++) oc[j][c] = 0.f;
    float d0 = 0.f, d1 = 0.f;

    const float cs2 = 0.12751879523595787f;  // (1/sqrt(128)) * log2(e)

    for (int t = 0; t < 16; t++) {
        __syncthreads();   // everyone done reading buffer we're about to fill

        if (t + 1 < 16) {
            uint32_t kb = sb + (((t + 1) & 1) ? SM_K1 : SM_K0);
            uint32_t vb = sb + (((t + 1) & 1) ? SM_V1 : SM_V0);
            const uint4* Kt = Kg + (t + 1) * 2048;
            #pragma unroll
            for (int j = 0; j < 8; j++) {
                int u = tid + j * 256;
                uint32_t so = (u >> 4) * 272 + (u & 15) * 16;
                cpasync16(kb + so, Kt + u);
                cpasync16(vb + so, Vt + (u >> 4) * 256 + (t + 1) * 16 + (u & 15));
            }
            cp_commit();
            cp_wait1();
        } else {
            cp_wait0();
        }
        __syncthreads();

        const __half* sK = (const __half*)(sm + ((t & 1) ? SM_K1 : SM_K0));
        const __half* sV = (const __half*)(sm + ((t & 1) ? SM_V1 : SM_V0));

        // ---- QK: S = Q @ K^T, warp tile 16 x 128 ----
        float sc[16][4];
        #pragma unroll
        for (int j = 0; j < 16; j++)
            #pragma unroll
            for (int c = 0; c < 4; c++) sc[j][c] = 0.f;

        #pragma unroll
        for (int kf = 0; kf < 8; kf++) {
            int k0 = kf * 16 + 2 * tau;
            #pragma unroll
            for (int j = 0; j < 16; j++) {
                int n = j * 8 + g;
                unsigned b0 = *(const unsigned*)&sK[n * 136 + k0];
                unsigned b1 = *(const unsigned*)&sK[n * 136 + k0 + 8];
                mma16816(sc[j], qa[kf], b0, b1);
            }
        }

        // ---- exp, denom, repack to PV A-frags (registers only) ----
        unsigned pa[8][4];
        #pragma unroll
        for (int j = 0; j < 16; j++) {
            float e0 = ex2f(sc[j][0] * cs2);
            float e1 = ex2f(sc[j][1] * cs2);
            float e2 = ex2f(sc[j][2] * cs2);
            float e3 = ex2f(sc[j][3] * cs2);
            d0 += e0 + e1;
            d1 += e2 + e3;
            pa[j >> 1][(j & 1) * 2]     = packh2(e0 - 1.f, e1 - 1.f);
            pa[j >> 1][(j & 1) * 2 + 1] = packh2(e2 - 1.f, e3 - 1.f);
        }

        // ---- PV: O += p' @ V, warp tile 16 x 128, k = 128 keys ----
        #pragma unroll
        for (int kf = 0; kf < 8; kf++) {
            int k0 = kf * 16 + 2 * tau;
            #pragma unroll
            for (int j = 0; j < 16; j++) {
                int n = j * 8 + g;
                unsigned b0 = *(const unsigned*)&sV[n * 136 + k0];
                unsigned b1 = *(const unsigned*)&sV[n * 136 + k0 + 8];
                mma16816(oc[j], pa[kf], b0, b1);
            }
        }
    }

    // ---- denominator quad-reduction (deterministic) ----
    d0 += __shfl_xor_sync(0xffffffffu, d0, 1);
    d0 += __shfl_xor_sync(0xffffffffu, d0, 2);
    d1 += __shfl_xor_sync(0xffffffffu, d1, 1);
    d1 += __shfl_xor_sync(0xffffffffu, d1, 2);
    float inv0 = 1.f / d0;
    float inv1 = 1.f / d1;

    // ---- epilogue: (p'V + colsum) / denom -> g_O ----
    const float* cs = (const float*)(sm + SM_CS);
    float* Og = g_O + hbase + (size_t)rb * 128 * DD;
    #pragma unroll
    for (int j = 0; j < 16; j++) {
        int c = j * 8 + 2 * tau;
        float2 csv = *(const float2*)&cs[c];
        float2 v0, v1;
        v0.x = (oc[j][0] + csv.x) * inv0;
        v0.y = (oc[j][1] + csv.y) * inv0;
        v1.x = (oc[j][2] + csv.x) * inv1;
        v1.y = (oc[j][3] + csv.y) * inv1;
        *(float2*)&Og[r0 * DD + c] = v0;
        *(float2*)&Og[(r0 + 8) * DD + c] = v1;
    }
}

// ---------------------------------------------------------------------------
// Sum over heads + 1e-8 * colsum correction -> d_out (float4 vectorized)
// ---------------------------------------------------------------------------
__global__ void reduce_kernel(float* __restrict__ out) {
    int i4 = blockIdx.x * 256 + threadIdx.x;    // 0 .. N*D/4-1
    int c4 = (i4 & 31) * 4;                      // col of first element
    float4 s = make_float4(0.f, 0.f, 0.f, 0.f);
    #pragma unroll 4
    for (int h = 0; h < HH; h++) {
        float4 o = *(const float4*)&g_O[(size_t)h * NN * DD + i4 * 4];
        const float* cs = &g_cs[h * DD + c4];
        s.x += o.x + 1e-8f * cs[0];
        s.y += o.y + 1e-8f * cs[1];
        s.z += o.z + 1e-8f * cs[2];
        s.w += o.w + 1e-8f * cs[3];
    }
    *(float4*)&out[i4 * 4] = s;
}

// ---------------------------------------------------------------------------
extern "C" void kernel_launch(void* const* d_in, const int* in_sizes, int n_in,
                              void* d_out, int out_size) {
    const float* X = (const float*)d_in[0];
    const float* W = (const float*)d_in[1];
    const float* V = (const float*)d_in[2];
    float* out = (float*)d_out;

    xconv_kernel<<<NN * DD / 256, 256>>>(X);
    precompute_kernel<<<dim3(NN / 64, HH, 2), 256>>>(X, W, V);
    colsum2_kernel<<<HH, 128>>>();

    cudaFuncSetAttribute(attn_kernel, cudaFuncAttributeMaxDynamicSharedMemorySize,
                         SM_TOTAL);
    attn_kernel<<<dim3(NN / 128, HH), 256, SM_TOTAL>>>();

    reduce_kernel<<<(NN * DD) / 1024, 256>>>(out);
}